// round 10
// baseline (speedup 1.0000x reference)
#include <cuda_runtime.h>
#include <cuda_bf16.h>

// Problem constants
#define BB 8
#define NN 128
#define CC 3
#define FF 64
#define KK 64

// Scratch for projections: p[row][kk], row = (b*N+n)*C+c (3072 rows), kk in [0,128):
// kk<64 -> p_i + b_vs (bias folded in), kk>=64 -> p_j.
__device__ float g_p[BB * NN * CC * 128];

// ---- packed f32x2 helpers (sm_100+) --------------------------------------
__device__ __forceinline__ unsigned long long add2(unsigned long long a, unsigned long long b) {
    unsigned long long r; asm("add.rn.f32x2 %0, %1, %2;" : "=l"(r) : "l"(a), "l"(b)); return r;
}
__device__ __forceinline__ unsigned long long mul2(unsigned long long a, unsigned long long b) {
    unsigned long long r; asm("mul.rn.f32x2 %0, %1, %2;" : "=l"(r) : "l"(a), "l"(b)); return r;
}
__device__ __forceinline__ unsigned long long fma2(unsigned long long a, unsigned long long b,
                                                   unsigned long long c) {
    unsigned long long r; asm("fma.rn.f32x2 %0, %1, %2, %3;" : "=l"(r) : "l"(a), "l"(b), "l"(c));
    return r;
}
__device__ __forceinline__ void unpk2(unsigned long long p, float& lo, float& hi) {
    asm("mov.b64 {%0, %1}, %2;" : "=f"(lo), "=f"(hi) : "l"(p));
}

// ---------------------------------------------------------------------------
// Kernel 1: p[row][kk] = sum_f vf[row][f] * ws[f][kk]  (+ b_vs[kk] if kk<64)
//   where ws[f][kk] = (kk<64) ? w_vs[f][kk] : w_vs[64+f][kk-64]
// 96 blocks x 256 threads; 32 rows per block. Ends with PDL launch_dependents.
// ---------------------------------------------------------------------------
__global__ __launch_bounds__(256)
void proj_kernel(const float* __restrict__ vf, const float* __restrict__ w,
                 const float* __restrict__ bvs)
{
    __shared__ float ws[FF * 128];   // 32 KB: rearranged weights [f][kk]
    __shared__ float vfs[32 * FF];   // 8 KB: this block's 32 vf rows

    const int tid = threadIdx.x;

    #pragma unroll
    for (int idx = tid; idx < FF * 128; idx += 256) {
        int f  = idx >> 7;
        int kk = idx & 127;
        ws[idx] = (kk < 64) ? w[f * 64 + kk] : w[(64 + f) * 64 + (kk - 64)];
    }

    const int r0 = blockIdx.x * 32;
    const float4* vf4 = reinterpret_cast<const float4*>(vf + (size_t)r0 * FF);
    float4* vfs4 = reinterpret_cast<float4*>(vfs);
    #pragma unroll
    for (int idx = tid; idx < 32 * (FF / 4); idx += 256)
        vfs4[idx] = vf4[idx];

    __syncthreads();

    const int kg = tid & 31;   // float4 group over kk
    const int rv = tid >> 5;   // 0..7

    float4 acc0 = make_float4(0.f, 0.f, 0.f, 0.f);
    float4 acc1 = acc0, acc2 = acc0, acc3 = acc0;

    const float4* ws4 = reinterpret_cast<const float4*>(ws); // [64][32]

    #pragma unroll 8
    for (int f = 0; f < FF; ++f) {
        float4 w4 = ws4[f * 32 + kg];
        float v0 = vfs[(rv     ) * FF + f];
        float v1 = vfs[(rv +  8) * FF + f];
        float v2 = vfs[(rv + 16) * FF + f];
        float v3 = vfs[(rv + 24) * FF + f];
        acc0.x += v0 * w4.x; acc0.y += v0 * w4.y; acc0.z += v0 * w4.z; acc0.w += v0 * w4.w;
        acc1.x += v1 * w4.x; acc1.y += v1 * w4.y; acc1.z += v1 * w4.z; acc1.w += v1 * w4.w;
        acc2.x += v2 * w4.x; acc2.y += v2 * w4.y; acc2.z += v2 * w4.z; acc2.w += v2 * w4.w;
        acc3.x += v3 * w4.x; acc3.y += v3 * w4.y; acc3.z += v3 * w4.z; acc3.w += v3 * w4.w;
    }

    if (kg < 16) {   // bias folded into the p_i half
        const float4 bv = reinterpret_cast<const float4*>(bvs)[kg];
        acc0.x += bv.x; acc0.y += bv.y; acc0.z += bv.z; acc0.w += bv.w;
        acc1.x += bv.x; acc1.y += bv.y; acc1.z += bv.z; acc1.w += bv.w;
        acc2.x += bv.x; acc2.y += bv.y; acc2.z += bv.z; acc2.w += bv.w;
        acc3.x += bv.x; acc3.y += bv.y; acc3.z += bv.z; acc3.w += bv.w;
    }

    float4* p4 = reinterpret_cast<float4*>(g_p); // [3072][32]
    p4[(size_t)(r0 + rv     ) * 32 + kg] = acc0;
    p4[(size_t)(r0 + rv +  8) * 32 + kg] = acc1;
    p4[(size_t)(r0 + rv + 16) * 32 + kg] = acc2;
    p4[(size_t)(r0 + rv + 24) * 32 + kg] = acc3;

    asm volatile("griddepcontrol.launch_dependents;" ::: "memory");
}

// ---------------------------------------------------------------------------
// Kernel 2: out[b,i,j,k] = relu( sum_c d[b,i,j,c] * (p_i'[b,i,c,k] + p_j[b,j,c,k]) )
// grid (jg=4, it=16, b=8) = 512 blocks x 256 threads; block = 8 i x 32 j.
// Thread = (kh in 0..7 [8 k values], jl in 0..31). pj (24 floats) in regs.
// Crossbar math: pi LDS.128 now hits only 8 distinct 16B addrs per warp
// -> 1 wavefront each (was 2). 9 wf per warp-iter for 1KB output (was 18/KB).
// ---------------------------------------------------------------------------
__global__ __launch_bounds__(256, 4)
void fuse_kernel(const float* __restrict__ dist,
                 float* __restrict__ out)
{
    __shared__ float4 pi_s[8 * 3 * 16];              // [(ii*3+c)][kquad]  6 KB
    __shared__ unsigned long long dist_p[8 * 96];    // packed (d,d)       6 KB

    const int tid = threadIdx.x;
    const int kh  = tid & 7;    // k-half-of-16: k = kh*8 .. kh*8+7
    const int jl  = tid >> 3;   // 0..31
    const int j0  = blockIdx.x * 32;
    const int i0  = blockIdx.y * 8;
    const int b   = blockIdx.z;

    // ---- Stage dist first (independent of proj's g_p) ----
    // Tile: 8 rows x 96 floats (32 j x 3 c). 192 float4 loads, packed to (d,d).
    if (tid < 192) {
        const int li  = 4 * tid;            // linear float index in tile
        const int ii  = li / 96;
        const int rem = li % 96;
        const float4 dv = *reinterpret_cast<const float4*>(
            dist + (size_t)(b * NN + i0 + ii) * NN * CC + j0 * CC + rem);
        unsigned long long p0, p1, p2, p3;
        asm("mov.b64 %0, {%1, %1};" : "=l"(p0) : "f"(dv.x));
        asm("mov.b64 %0, {%1, %1};" : "=l"(p1) : "f"(dv.y));
        asm("mov.b64 %0, {%1, %1};" : "=l"(p2) : "f"(dv.z));
        asm("mov.b64 %0, {%1, %1};" : "=l"(p3) : "f"(dv.w));
        dist_p[li]     = p0;
        dist_p[li + 1] = p1;
        dist_p[li + 2] = p2;
        dist_p[li + 3] = p3;
    }

    // ---- PDL wait: proj's g_p stores visible after this ----
    asm volatile("griddepcontrol.wait;" ::: "memory");

    const float4* p4 = reinterpret_cast<const float4*>(g_p);        // [3072][32]
    const ulonglong2* p4u = reinterpret_cast<const ulonglong2*>(g_p);
    const int rowbase = (b * NN + i0) * CC;                         // 24 rows

    // pj for this thread's (j, k-half): 3 c x 2 ulonglong2 = 24 floats in regs
    const int j = j0 + jl;
    const int rowj = (b * NN + j) * CC;
    const int kb = 16 + kh * 2;   // float4 index of this k-half in the pj half
    const ulonglong2 pj0a = p4u[(size_t)(rowj    ) * 32 + kb];
    const ulonglong2 pj0b = p4u[(size_t)(rowj    ) * 32 + kb + 1];
    const ulonglong2 pj1a = p4u[(size_t)(rowj + 1) * 32 + kb];
    const ulonglong2 pj1b = p4u[(size_t)(rowj + 1) * 32 + kb + 1];
    const ulonglong2 pj2a = p4u[(size_t)(rowj + 2) * 32 + kb];
    const ulonglong2 pj2b = p4u[(size_t)(rowj + 2) * 32 + kb + 1];

    // Stage p_i: 384 float4 (24 rows x 16 float4)
    {
        const int r = tid >> 4, kk = tid & 15;
        pi_s[tid] = p4[(size_t)(rowbase + r) * 32 + kk];
        if (tid < 128) {
            const int idx2 = tid + 256;
            const int r2 = idx2 >> 4, kk2 = idx2 & 15;
            pi_s[idx2] = p4[(size_t)(rowbase + r2) * 32 + kk2];
        }
    }

    __syncthreads();

    const ulonglong2* pi_u = reinterpret_cast<const ulonglong2*>(pi_s);
    const int kq2 = kh * 2;   // float4/ulonglong2 index within pi row
    float* obase = out + ((size_t)(b * NN + i0) * NN + j) * KK + kh * 8;

    #pragma unroll
    for (int ii = 0; ii < 8; ++ii) {
        const ulonglong2 pi0a = pi_u[(ii * 3 + 0) * 16 + kq2];
        const ulonglong2 pi0b = pi_u[(ii * 3 + 0) * 16 + kq2 + 1];
        const ulonglong2 pi1a = pi_u[(ii * 3 + 1) * 16 + kq2];
        const ulonglong2 pi1b = pi_u[(ii * 3 + 1) * 16 + kq2 + 1];
        const ulonglong2 pi2a = pi_u[(ii * 3 + 2) * 16 + kq2];
        const ulonglong2 pi2b = pi_u[(ii * 3 + 2) * 16 + kq2 + 1];
        const unsigned long long d0 = dist_p[ii * 96 + jl * 3 + 0];
        const unsigned long long d1 = dist_p[ii * 96 + jl * 3 + 1];
        const unsigned long long d2 = dist_p[ii * 96 + jl * 3 + 2];

        unsigned long long a0 = mul2(d0, add2(pi0a.x, pj0a.x));
        unsigned long long a1 = mul2(d0, add2(pi0a.y, pj0a.y));
        unsigned long long a2 = mul2(d0, add2(pi0b.x, pj0b.x));
        unsigned long long a3 = mul2(d0, add2(pi0b.y, pj0b.y));

        a0 = fma2(d1, add2(pi1a.x, pj1a.x), a0);
        a1 = fma2(d1, add2(pi1a.y, pj1a.y), a1);
        a2 = fma2(d1, add2(pi1b.x, pj1b.x), a2);
        a3 = fma2(d1, add2(pi1b.y, pj1b.y), a3);

        a0 = fma2(d2, add2(pi2a.x, pj2a.x), a0);
        a1 = fma2(d2, add2(pi2a.y, pj2a.y), a1);
        a2 = fma2(d2, add2(pi2b.x, pj2b.x), a2);
        a3 = fma2(d2, add2(pi2b.y, pj2b.y), a3);

        float4 lo, hi;
        unpk2(a0, lo.x, lo.y);
        unpk2(a1, lo.z, lo.w);
        unpk2(a2, hi.x, hi.y);
        unpk2(a3, hi.z, hi.w);
        lo.x = fmaxf(lo.x, 0.f); lo.y = fmaxf(lo.y, 0.f);
        lo.z = fmaxf(lo.z, 0.f); lo.w = fmaxf(lo.w, 0.f);
        hi.x = fmaxf(hi.x, 0.f); hi.y = fmaxf(hi.y, 0.f);
        hi.z = fmaxf(hi.z, 0.f); hi.w = fmaxf(hi.w, 0.f);

        float* op = obase + (size_t)ii * NN * KK;
        reinterpret_cast<float4*>(op)[0] = lo;
        reinterpret_cast<float4*>(op)[1] = hi;
    }
}

extern "C" void kernel_launch(void* const* d_in, const int* in_sizes, int n_in,
                              void* d_out, int out_size)
{
    const float* vf   = (const float*)d_in[0]; // (8,128,3,64)
    const float* dist = (const float*)d_in[1]; // (8,128,128,3)
    const float* w_vs = (const float*)d_in[2]; // (128,64)
    const float* b_vs = (const float*)d_in[3]; // (64,)
    float* out = (float*)d_out;                // (8,128,128,64)

    (void)in_sizes; (void)n_in; (void)out_size;

    proj_kernel<<<96, 256>>>(vf, w_vs, b_vs);

    // PDL launch of fuse_kernel (overlaps proj's tail; data dep via wait)
    cudaLaunchConfig_t cfg = {};
    cfg.gridDim  = dim3(4, 16, 8);
    cfg.blockDim = dim3(256, 1, 1);
    cfg.dynamicSmemBytes = 0;
    cfg.stream = 0;
    cudaLaunchAttribute attr[1];
    attr[0].id = cudaLaunchAttributeProgrammaticStreamSerialization;
    attr[0].val.programmaticStreamSerializationAllowed = 1;
    cfg.attrs = attr;
    cfg.numAttrs = 1;
    cudaError_t e = cudaLaunchKernelEx(&cfg, fuse_kernel, dist, (float*)out);
    if (e != cudaSuccess) {
        fuse_kernel<<<dim3(4, 16, 8), 256>>>(dist, out);
    }
}

// round 12
// speedup vs baseline: 1.4068x; 1.4068x over previous
#include <cuda_runtime.h>
#include <cuda_bf16.h>

// Problem constants
#define BB 8
#define NN 128
#define CC 3
#define FF 64
#define KK 64

// Scratch for projections: p[row][kk], row = (b*N+n)*C+c (3072 rows), kk in [0,128):
// kk<64 -> p_i + b_vs (bias folded in), kk>=64 -> p_j.
__device__ float g_p[BB * NN * CC * 128];

// ---- packed f32x2 helpers (sm_100+) --------------------------------------
__device__ __forceinline__ unsigned long long add2(unsigned long long a, unsigned long long b) {
    unsigned long long r; asm("add.rn.f32x2 %0, %1, %2;" : "=l"(r) : "l"(a), "l"(b)); return r;
}
__device__ __forceinline__ unsigned long long mul2(unsigned long long a, unsigned long long b) {
    unsigned long long r; asm("mul.rn.f32x2 %0, %1, %2;" : "=l"(r) : "l"(a), "l"(b)); return r;
}
__device__ __forceinline__ unsigned long long fma2(unsigned long long a, unsigned long long b,
                                                   unsigned long long c) {
    unsigned long long r; asm("fma.rn.f32x2 %0, %1, %2, %3;" : "=l"(r) : "l"(a), "l"(b), "l"(c));
    return r;
}
__device__ __forceinline__ void unpk2(unsigned long long p, float& lo, float& hi) {
    asm("mov.b64 {%0, %1}, %2;" : "=f"(lo), "=f"(hi) : "l"(p));
}

// ---------------------------------------------------------------------------
// Kernel 1: p[row][kk] = sum_f vf[row][f] * ws[f][kk]  (+ b_vs[kk] if kk<64)
//   where ws[f][kk] = (kk<64) ? w_vs[f][kk] : w_vs[64+f][kk-64]
// 96 blocks x 256 threads; 32 rows per block. Ends with PDL launch_dependents.
// ---------------------------------------------------------------------------
__global__ __launch_bounds__(256)
void proj_kernel(const float* __restrict__ vf, const float* __restrict__ w,
                 const float* __restrict__ bvs)
{
    __shared__ float ws[FF * 128];   // 32 KB: rearranged weights [f][kk]
    __shared__ float vfs[32 * FF];   // 8 KB: this block's 32 vf rows

    const int tid = threadIdx.x;

    #pragma unroll
    for (int idx = tid; idx < FF * 128; idx += 256) {
        int f  = idx >> 7;
        int kk = idx & 127;
        ws[idx] = (kk < 64) ? w[f * 64 + kk] : w[(64 + f) * 64 + (kk - 64)];
    }

    const int r0 = blockIdx.x * 32;
    const float4* vf4 = reinterpret_cast<const float4*>(vf + (size_t)r0 * FF);
    float4* vfs4 = reinterpret_cast<float4*>(vfs);
    #pragma unroll
    for (int idx = tid; idx < 32 * (FF / 4); idx += 256)
        vfs4[idx] = vf4[idx];

    __syncthreads();

    const int kg = tid & 31;   // float4 group over kk
    const int rv = tid >> 5;   // 0..7

    float4 acc0 = make_float4(0.f, 0.f, 0.f, 0.f);
    float4 acc1 = acc0, acc2 = acc0, acc3 = acc0;

    const float4* ws4 = reinterpret_cast<const float4*>(ws); // [64][32]

    #pragma unroll 8
    for (int f = 0; f < FF; ++f) {
        float4 w4 = ws4[f * 32 + kg];
        float v0 = vfs[(rv     ) * FF + f];
        float v1 = vfs[(rv +  8) * FF + f];
        float v2 = vfs[(rv + 16) * FF + f];
        float v3 = vfs[(rv + 24) * FF + f];
        acc0.x += v0 * w4.x; acc0.y += v0 * w4.y; acc0.z += v0 * w4.z; acc0.w += v0 * w4.w;
        acc1.x += v1 * w4.x; acc1.y += v1 * w4.y; acc1.z += v1 * w4.z; acc1.w += v1 * w4.w;
        acc2.x += v2 * w4.x; acc2.y += v2 * w4.y; acc2.z += v2 * w4.z; acc2.w += v2 * w4.w;
        acc3.x += v3 * w4.x; acc3.y += v3 * w4.y; acc3.z += v3 * w4.z; acc3.w += v3 * w4.w;
    }

    if (kg < 16) {   // bias folded into the p_i half
        const float4 bv = reinterpret_cast<const float4*>(bvs)[kg];
        acc0.x += bv.x; acc0.y += bv.y; acc0.z += bv.z; acc0.w += bv.w;
        acc1.x += bv.x; acc1.y += bv.y; acc1.z += bv.z; acc1.w += bv.w;
        acc2.x += bv.x; acc2.y += bv.y; acc2.z += bv.z; acc2.w += bv.w;
        acc3.x += bv.x; acc3.y += bv.y; acc3.z += bv.z; acc3.w += bv.w;
    }

    float4* p4 = reinterpret_cast<float4*>(g_p); // [3072][32]
    p4[(size_t)(r0 + rv     ) * 32 + kg] = acc0;
    p4[(size_t)(r0 + rv +  8) * 32 + kg] = acc1;
    p4[(size_t)(r0 + rv + 16) * 32 + kg] = acc2;
    p4[(size_t)(r0 + rv + 24) * 32 + kg] = acc3;

    asm volatile("griddepcontrol.launch_dependents;" ::: "memory");
}

// ---------------------------------------------------------------------------
// Kernel 2: out[b,i,j,k] = relu( sum_c d[b,i,j,c] * (p_i'[b,i,c,k] + p_j[b,j,c,k]) )
// grid (jg=8, it=16, b=8) = 1024 blocks x 256 threads; block = 8 i x 16 j.
// R4/R5-proven geometry: (256,6) -> 40 regs, 6 CTAs/SM. pi staged in smem,
// pj in regs, packed f32x2 math. NEW: dist staged pre-packed (d,d) in a
// 32B-padded [ii][jl][c0,c1,c2,pad] layout -> loop reads it as LDS.128+LDS.64
// (2 instr / 2 wavefronts instead of 3/3).
// ---------------------------------------------------------------------------
__global__ __launch_bounds__(256, 6)
void fuse_kernel(const float* __restrict__ dist,
                 float* __restrict__ out)
{
    __shared__ float4 pi_s[8 * 3 * 16];              // [(ii*3+c)][kq]   6 KB
    __shared__ unsigned long long dist_p[8 * 16 * 4];// [ii][jl][c,pad]  4 KB

    const int tid = threadIdx.x;
    const int kq  = tid & 15;   // k quad: k = kq*4
    const int jl  = tid >> 4;   // 0..15
    const int j0  = blockIdx.x * 16;
    const int i0  = blockIdx.y * 8;
    const int b   = blockIdx.z;

    // ---- Stage dist first (independent of proj's g_p) ----
    // Tile = 8 rows x 48 floats = 384 floats; 192 threads x float2.
    if (tid < 192) {
        const int li  = 2 * tid;             // linear float index in tile
        const int ii  = li / 48;
        const int rem = li % 48;
        const float2 dv = *reinterpret_cast<const float2*>(
            dist + (size_t)(b * NN + i0 + ii) * NN * CC + j0 * CC + rem);
        unsigned long long p0, p1;
        asm("mov.b64 %0, {%1, %1};" : "=l"(p0) : "f"(dv.x));
        asm("mov.b64 %0, {%1, %1};" : "=l"(p1) : "f"(dv.y));
        const int jl0 = rem / 3,       c0 = rem - 3 * jl0;
        const int jl1 = (rem + 1) / 3, c1 = (rem + 1) - 3 * jl1;
        dist_p[(ii * 16 + jl0) * 4 + c0] = p0;
        dist_p[(ii * 16 + jl1) * 4 + c1] = p1;
    }

    // ---- PDL wait: proj's g_p stores visible after this ----
    asm volatile("griddepcontrol.wait;" ::: "memory");

    const float4* p4 = reinterpret_cast<const float4*>(g_p);        // [3072][32]
    const ulonglong2* p4u = reinterpret_cast<const ulonglong2*>(g_p);
    const int rowbase = (b * NN + i0) * CC;                         // 24 rows

    // pj in registers (issued before pi staging: shares the MLP window)
    const int j = j0 + jl;
    const int rowj = (b * NN + j) * CC;
    const ulonglong2 pj0 = p4u[(size_t)(rowj    ) * 32 + 16 + kq];
    const ulonglong2 pj1 = p4u[(size_t)(rowj + 1) * 32 + 16 + kq];
    const ulonglong2 pj2 = p4u[(size_t)(rowj + 2) * 32 + 16 + kq];

    // Stage p_i: 384 float4 (24 rows x 16 float4)
    {
        const int r = tid >> 4, kk = tid & 15;
        pi_s[tid] = p4[(size_t)(rowbase + r) * 32 + kk];
        if (tid < 128) {
            const int idx2 = tid + 256;
            const int r2 = idx2 >> 4, kk2 = idx2 & 15;
            pi_s[idx2] = p4[(size_t)(rowbase + r2) * 32 + kk2];
        }
    }

    __syncthreads();

    const ulonglong2* pi_u = reinterpret_cast<const ulonglong2*>(pi_s);
    float4* obase = reinterpret_cast<float4*>(out)
                  + ((size_t)(b * NN + i0) * NN + j) * 16 + kq;

    #pragma unroll
    for (int ii = 0; ii < 8; ++ii) {
        const ulonglong2 pi0 = pi_u[(ii * 3 + 0) * 16 + kq];
        const ulonglong2 pi1 = pi_u[(ii * 3 + 1) * 16 + kq];
        const ulonglong2 pi2 = pi_u[(ii * 3 + 2) * 16 + kq];
        // dist for (ii, jl): one LDS.128 (c0,c1) + one LDS.64 (c2)
        const ulonglong2 d01 =
            *reinterpret_cast<const ulonglong2*>(&dist_p[(ii * 16 + jl) * 4]);
        const unsigned long long d2 = dist_p[(ii * 16 + jl) * 4 + 2];

        unsigned long long alo = mul2(d01.x, add2(pi0.x, pj0.x));
        alo = fma2(d01.y, add2(pi1.x, pj1.x), alo);
        alo = fma2(d2,    add2(pi2.x, pj2.x), alo);

        unsigned long long ahi = mul2(d01.x, add2(pi0.y, pj0.y));
        ahi = fma2(d01.y, add2(pi1.y, pj1.y), ahi);
        ahi = fma2(d2,    add2(pi2.y, pj2.y), ahi);

        float4 a;
        unpk2(alo, a.x, a.y);
        unpk2(ahi, a.z, a.w);
        a.x = fmaxf(a.x, 0.f);
        a.y = fmaxf(a.y, 0.f);
        a.z = fmaxf(a.z, 0.f);
        a.w = fmaxf(a.w, 0.f);

        obase[(size_t)ii * NN * 16] = a;
    }
}

extern "C" void kernel_launch(void* const* d_in, const int* in_sizes, int n_in,
                              void* d_out, int out_size)
{
    const float* vf   = (const float*)d_in[0]; // (8,128,3,64)
    const float* dist = (const float*)d_in[1]; // (8,128,128,3)
    const float* w_vs = (const float*)d_in[2]; // (128,64)
    const float* b_vs = (const float*)d_in[3]; // (64,)
    float* out = (float*)d_out;                // (8,128,128,64)

    (void)in_sizes; (void)n_in; (void)out_size;

    proj_kernel<<<96, 256>>>(vf, w_vs, b_vs);

    // PDL launch of fuse_kernel (overlaps proj's tail; data dep via wait)
    cudaLaunchConfig_t cfg = {};
    cfg.gridDim  = dim3(8, 16, 8);
    cfg.blockDim = dim3(256, 1, 1);
    cfg.dynamicSmemBytes = 0;
    cfg.stream = 0;
    cudaLaunchAttribute attr[1];
    attr[0].id = cudaLaunchAttributeProgrammaticStreamSerialization;
    attr[0].val.programmaticStreamSerializationAllowed = 1;
    cfg.attrs = attr;
    cfg.numAttrs = 1;
    cudaError_t e = cudaLaunchKernelEx(&cfg, fuse_kernel, dist, (float*)out);
    if (e != cudaSuccess) {
        fuse_kernel<<<dim3(8, 16, 8), 256>>>(dist, out);
    }
}